// round 12
// baseline (speedup 1.0000x reference)
#include <cuda_runtime.h>
#include <cstdint>

#define EPS 1e-6f
#define BLOCK 128
#define WARPS (BLOCK / 32)
#define RP4 7                  // float4 per row slot (28 words): LDS.128 stride-28 conflict-free
#define TILES 4                // 32-row tiles per warp => 128 rows/warp, 512 rows/CTA
#define REGION_F4 (32 * RP4)   // 224 float4 per (warp, buf, tensor) region

__device__ float g_sumL = 0.0f;
__device__ float g_sumC = 0.0f;
__device__ unsigned int g_count = 0;

__device__ __forceinline__ float norm2f(float x, float y) {
    return sqrtf(x * x + y * y);
}

__device__ __forceinline__ void cp_async16(uint32_t smem_addr, const void* gptr) {
    asm volatile("cp.async.cg.shared.global [%0], [%1], 16;\n"
                 :: "r"(smem_addr), "l"(gptr));
}
__device__ __forceinline__ void cp_commit() {
    asm volatile("cp.async.commit_group;\n" ::: "memory");
}
template <int N>
__device__ __forceinline__ void cp_wait() {
    asm volatile("cp.async.wait_group %0;\n" :: "n"(N) : "memory");
}

// Per-row loss from 24-float stride-1 views.
__device__ __forceinline__ void row_loss(const float* __restrict__ P,
                                         const float* __restrict__ G,
                                         float& L, float& cnt)
{
    float px[4], py[4], gx[4], gy[4];
    int nv = 0;
    #pragma unroll
    for (int k = 0; k < 8; k++) {
        const float ax = P[3*k], ay = P[3*k+1], az = P[3*k+2];
        const float bx = G[3*k], by = G[3*k+1], bz = G[3*k+2];
        if ((az > 0.5f) && (bz > 0.5f)) {
            if (nv == 0)      { px[0]=ax; py[0]=ay; gx[0]=bx; gy[0]=by; }
            else if (nv == 1) { px[1]=ax; py[1]=ay; gx[1]=bx; gy[1]=by; }
            else if (nv == 2) { px[2]=ax; py[2]=ay; gx[2]=bx; gy[2]=by; }
            else if (nv == 3) { px[3]=ax; py[3]=ay; gx[3]=bx; gy[3]=by; }
            nv++;
        }
    }
    if (nv < 4) return;

    const float pred_cr = __fdividef(norm2f(px[2]-px[0], py[2]-py[0]),
                                     norm2f(px[3]-px[1], py[3]-py[1]) + EPS);
    const float gt_cr   = __fdividef(norm2f(gx[2]-gx[0], gy[2]-gy[0]),
                                     norm2f(gx[3]-gx[1], gy[3]-gy[1]) + EPS);
    const float L_shape = fabsf(pred_cr - gt_cr);

    const float v12x = px[1]-px[0], v12y = py[1]-py[0];
    const float v23x = px[2]-px[1], v23y = py[2]-py[1];
    const float v34x = px[3]-px[2], v34y = py[3]-py[2];
    const float v41x = px[0]-px[3], v41y = py[0]-py[3];
    const float l12 = norm2f(v12x, v12y);
    const float l23 = norm2f(v23x, v23y);
    const float l34 = norm2f(v34x, v34y);
    const float l41 = norm2f(v41x, v41y);

    const float par1 = __fdividef(fabsf(l12 - l34), l12 + l34 + EPS);
    const float par2 = __fdividef(fabsf(l23 - l41), l23 + l41 + EPS);
    const float dot1 = fabsf(__fdividef(v12x*v41x + v12y*v41y, l12*l41 + EPS));
    const float dot2 = fabsf(__fdividef(v12x*v23x + v12y*v23y, l12*l23 + EPS));
    const float dot3 = fabsf(__fdividef(v23x*v34x + v23y*v34y, l23*l34 + EPS));
    const float dot4 = fabsf(__fdividef(v34x*v41x + v34y*v41y, l34*l41 + EPS));
    const float L_edge = (par1 + par2) * 0.5f + (dot1 + dot2 + dot3 + dot4) * 0.25f;

    float dist = 0.0f;
    #pragma unroll
    for (int i = 0; i < 4; i++)
        dist += norm2f(px[i]-gx[i], py[i]-gy[i]);
    dist *= 0.25f;

    const float pax1 = px[1]-px[0], pay1 = py[1]-py[0];
    const float pax2 = px[2]-px[0], pay2 = py[2]-py[0];
    const float pax3 = px[3]-px[0], pay3 = py[3]-py[0];
    const float pred_area = 0.5f * fabsf(pax1*pay2 - pay1*pax2)
                          + 0.5f * fabsf(pax2*pay3 - pay2*pax3);
    const float gax1 = gx[1]-gx[0], gay1 = gy[1]-gy[0];
    const float gax2 = gx[2]-gx[0], gay2 = gy[2]-gy[0];
    const float gax3 = gx[3]-gx[0], gay3 = gy[3]-gy[0];
    const float gt_area = 0.5f * fabsf(gax1*gay2 - gay1*gax2)
                        + 0.5f * fabsf(gax2*gay3 - gay2*gax3);
    const float area_ratio = __fdividef(fabsf(pred_area - gt_area), gt_area + EPS);

    const float pmx = 0.25f * (px[0]+px[1]+px[2]+px[3]);
    const float pmy = 0.25f * (py[0]+py[1]+py[2]+py[3]);
    const float gmx = 0.25f * (gx[0]+gx[1]+gx[2]+gx[3]);
    const float gmy = 0.25f * (gy[0]+gy[1]+gy[2]+gy[3]);
    float rel_cons = 0.0f;
    #pragma unroll
    for (int i = 0; i < 4; i++)
        rel_cons += norm2f((px[i]-pmx) - (gx[i]-gmx),
                           (py[i]-pmy) - (gy[i]-gmy));
    rel_cons *= 0.25f;

    const float L_pos = 0.4f * dist + 0.3f * area_ratio + 0.3f * rel_cons;

    L   += 0.4f * L_shape + 0.3f * L_edge + 0.3f * L_pos;
    cnt += 1.0f;
}

__global__ void __launch_bounds__(BLOCK)
gsc_fused_kernel(const float* __restrict__ pred,
                 const float* __restrict__ gt,
                 float* __restrict__ out,
                 int nrows)
{
    // [warp][buf][tensor] regions of 224 float4 each: 4*2*2*224*16 = 57344 B
    __shared__ float4 smem[WARPS * 2 * 2 * REGION_F4];
    __shared__ float sL[WARPS];
    __shared__ float sC[WARPS];
    __shared__ int sIsLast;

    const int tid  = threadIdx.x;
    const int warp = tid >> 5;
    const int lane = tid & 31;

    const int warp_row0 = (blockIdx.x * WARPS + warp) * (32 * TILES);

    float L = 0.0f, cnt = 0.0f;

    if (warp_row0 + 32 * TILES <= nrows) {
        // ============ fast path: cp.async double-buffered per-warp pipeline ============
        // Per-lane smem scatter offsets (same for every tile): j = lane + 32*i
        uint32_t dstP[6], dstG[6];
        {
            const uint32_t base = (uint32_t)__cvta_generic_to_shared(smem);
            #pragma unroll
            for (int i = 0; i < 6; i++) {
                const int j = lane + 32 * i;
                const int slot = (j / 6) * RP4 + (j % 6);
                dstP[i] = base + (uint32_t)(((warp * 2 + 0) * 2 + 0) * REGION_F4 + slot) * 16u;
                dstG[i] = base + (uint32_t)(((warp * 2 + 0) * 2 + 1) * REGION_F4 + slot) * 16u;
            }
        }
        const uint32_t bufstride = (uint32_t)(2 * REGION_F4) * 16u;  // buf0 -> buf1 bytes

        // issue tile 0 into buf 0
        {
            const float4* p4 = reinterpret_cast<const float4*>(pred) + (size_t)warp_row0 * 6;
            const float4* q4 = reinterpret_cast<const float4*>(gt)   + (size_t)warp_row0 * 6;
            #pragma unroll
            for (int i = 0; i < 6; i++) cp_async16(dstP[i], p4 + lane + 32 * i);
            #pragma unroll
            for (int i = 0; i < 6; i++) cp_async16(dstG[i], q4 + lane + 32 * i);
            cp_commit();
        }

        #pragma unroll
        for (int t = 0; t < TILES; t++) {
            const uint32_t cbuf = (t & 1) ? bufstride : 0u;

            if (t + 1 < TILES) {
                const uint32_t nbuf = ((t + 1) & 1) ? bufstride : 0u;
                const int nrow0 = warp_row0 + 32 * (t + 1);
                const float4* p4 = reinterpret_cast<const float4*>(pred) + (size_t)nrow0 * 6;
                const float4* q4 = reinterpret_cast<const float4*>(gt)   + (size_t)nrow0 * 6;
                #pragma unroll
                for (int i = 0; i < 6; i++) cp_async16(dstP[i] + nbuf, p4 + lane + 32 * i);
                #pragma unroll
                for (int i = 0; i < 6; i++) cp_async16(dstG[i] + nbuf, q4 + lane + 32 * i);
                cp_commit();
                cp_wait<1>();   // tile t's group complete
            } else {
                cp_wait<0>();
            }
            __syncwarp();

            // compute own row: 12 LDS.128 at word-stride 28 (conflict-free)
            const float4* rP = &smem[(size_t)(warp * 2 + 0) * 2 * REGION_F4] + lane * RP4;
            const float4* rG = rP + REGION_F4;
            const float4* cP = reinterpret_cast<const float4*>(
                                   reinterpret_cast<const char*>(rP) + cbuf);
            const float4* cG = reinterpret_cast<const float4*>(
                                   reinterpret_cast<const char*>(rG) + cbuf);

            float pv[24], gv[24];
            #pragma unroll
            for (int i = 0; i < 6; i++) {
                const float4 v = cP[i];
                pv[4*i+0] = v.x; pv[4*i+1] = v.y; pv[4*i+2] = v.z; pv[4*i+3] = v.w;
            }
            #pragma unroll
            for (int i = 0; i < 6; i++) {
                const float4 v = cG[i];
                gv[4*i+0] = v.x; gv[4*i+1] = v.y; gv[4*i+2] = v.z; gv[4*i+3] = v.w;
            }

            row_loss(pv, gv, L, cnt);
            __syncwarp();   // all lanes done with cbuf before it is re-issued
        }
    } else {
        // ============ ragged tail: direct strided, bounds-checked ============
        #pragma unroll
        for (int t = 0; t < TILES; t++) {
            const int row = warp_row0 + 32 * t + lane;
            if (row < nrows) {
                float pv[24], gv[24];
                const float4* p4 = reinterpret_cast<const float4*>(pred + (size_t)row * 24);
                const float4* q4 = reinterpret_cast<const float4*>(gt   + (size_t)row * 24);
                #pragma unroll
                for (int i = 0; i < 6; i++) {
                    float4 a = p4[i];
                    pv[4*i+0]=a.x; pv[4*i+1]=a.y; pv[4*i+2]=a.z; pv[4*i+3]=a.w;
                    float4 b = q4[i];
                    gv[4*i+0]=b.x; gv[4*i+1]=b.y; gv[4*i+2]=b.z; gv[4*i+3]=b.w;
                }
                row_loss(pv, gv, L, cnt);
            }
        }
    }

    // ---- block reduction ----
    #pragma unroll
    for (int off = 16; off > 0; off >>= 1) {
        L   += __shfl_down_sync(0xffffffffu, L,   off);
        cnt += __shfl_down_sync(0xffffffffu, cnt, off);
    }
    if (lane == 0) { sL[warp] = L; sC[warp] = cnt; }
    __syncthreads();

    if (tid == 0) {
        float tL = 0.0f, tC = 0.0f;
        #pragma unroll
        for (int w = 0; w < WARPS; w++) { tL += sL[w]; tC += sC[w]; }
        atomicAdd(&g_sumL, tL);
        atomicAdd(&g_sumC, tC);
        __threadfence();
        const unsigned int old = atomicAdd(&g_count, 1u);
        sIsLast = (old == gridDim.x - 1) ? 1 : 0;
    }
    __syncthreads();

    if (sIsLast && tid == 0) {
        const float tL = g_sumL;
        const float tC = g_sumC;
        out[0] = (tC > 0.5f) ? (tL / tC) : 0.0f;
        g_sumL = 0.0f;
        g_sumC = 0.0f;
        g_count = 0;
    }
}

extern "C" void kernel_launch(void* const* d_in, const int* in_sizes, int n_in,
                              void* d_out, int out_size)
{
    const float* pred = (const float*)d_in[0];
    const float* gt   = (const float*)d_in[1];
    float* out = (float*)d_out;

    const int nrows = in_sizes[0] / 24;                     // 524288
    const int rows_per_cta = WARPS * 32 * TILES;            // 512
    const int nblocks = (nrows + rows_per_cta - 1) / rows_per_cta;   // 1024

    gsc_fused_kernel<<<nblocks, BLOCK>>>(pred, gt, out, nrows);
}

// round 13
// speedup vs baseline: 1.2667x; 1.2667x over previous
#include <cuda_runtime.h>

#define EPS 1e-6f
#define BLOCK 256

__device__ float g_sumL = 0.0f;
__device__ float g_sumC = 0.0f;
__device__ unsigned int g_count = 0;

__device__ __forceinline__ float norm2f(float x, float y) {
    return sqrtf(x * x + y * y);
}

__global__ void __launch_bounds__(BLOCK)
gsc_fused_kernel(const float* __restrict__ pred,
                 const float* __restrict__ gt,
                 float* __restrict__ out,
                 int nrows)
{
    __shared__ float sL[BLOCK / 32];
    __shared__ float sC[BLOCK / 32];
    __shared__ int sIsLast;

    const int tid = threadIdx.x;
    const int row = blockIdx.x * BLOCK + tid;

    float L = 0.0f, cnt = 0.0f;

    if (row < nrows) {
        // Row = 24 floats = 6 float4 (96B, 16B aligned). 12 batched LDG.128 -> MLP 12.
        const float4* p4 = reinterpret_cast<const float4*>(pred + (size_t)row * 24);
        const float4* q4 = reinterpret_cast<const float4*>(gt   + (size_t)row * 24);

        float4 rp[6], rg[6];
        #pragma unroll
        for (int i = 0; i < 6; i++) rp[i] = p4[i];
        #pragma unroll
        for (int i = 0; i < 6; i++) rg[i] = q4[i];

        float pv[24], gv[24];
        #pragma unroll
        for (int i = 0; i < 6; i++) {
            pv[4*i+0] = rp[i].x; pv[4*i+1] = rp[i].y; pv[4*i+2] = rp[i].z; pv[4*i+3] = rp[i].w;
            gv[4*i+0] = rg[i].x; gv[4*i+1] = rg[i].y; gv[4*i+2] = rg[i].z; gv[4*i+3] = rg[i].w;
        }

        // First 4 visible keypoints in stable order.
        float px[4], py[4], gx[4], gy[4];
        int nv = 0;
        #pragma unroll
        for (int k = 0; k < 8; k++) {
            const bool vis = (pv[3*k+2] > 0.5f) && (gv[3*k+2] > 0.5f);
            if (vis) {
                const float ax = pv[3*k], ay = pv[3*k+1];
                const float bx = gv[3*k], by = gv[3*k+1];
                if (nv == 0)      { px[0]=ax; py[0]=ay; gx[0]=bx; gy[0]=by; }
                else if (nv == 1) { px[1]=ax; py[1]=ay; gx[1]=bx; gy[1]=by; }
                else if (nv == 2) { px[2]=ax; py[2]=ay; gx[2]=bx; gy[2]=by; }
                else if (nv == 3) { px[3]=ax; py[3]=ay; gx[3]=bx; gy[3]=by; }
                nv++;
            }
        }

        if (nv >= 4) {
            // ---- L_shape ----
            const float pred_cr = __fdividef(norm2f(px[2]-px[0], py[2]-py[0]),
                                             norm2f(px[3]-px[1], py[3]-py[1]) + EPS);
            const float gt_cr   = __fdividef(norm2f(gx[2]-gx[0], gy[2]-gy[0]),
                                             norm2f(gx[3]-gx[1], gy[3]-gy[1]) + EPS);
            const float L_shape = fabsf(pred_cr - gt_cr);

            // ---- L_edge ----
            const float v12x = px[1]-px[0], v12y = py[1]-py[0];
            const float v23x = px[2]-px[1], v23y = py[2]-py[1];
            const float v34x = px[3]-px[2], v34y = py[3]-py[2];
            const float v41x = px[0]-px[3], v41y = py[0]-py[3];
            const float l12 = norm2f(v12x, v12y);
            const float l23 = norm2f(v23x, v23y);
            const float l34 = norm2f(v34x, v34y);
            const float l41 = norm2f(v41x, v41y);

            const float par1 = __fdividef(fabsf(l12 - l34), l12 + l34 + EPS);
            const float par2 = __fdividef(fabsf(l23 - l41), l23 + l41 + EPS);
            const float dot1 = fabsf(__fdividef(v12x*v41x + v12y*v41y, l12*l41 + EPS));
            const float dot2 = fabsf(__fdividef(v12x*v23x + v12y*v23y, l12*l23 + EPS));
            const float dot3 = fabsf(__fdividef(v23x*v34x + v23y*v34y, l23*l34 + EPS));
            const float dot4 = fabsf(__fdividef(v34x*v41x + v34y*v41y, l34*l41 + EPS));
            const float L_edge = (par1 + par2) * 0.5f + (dot1 + dot2 + dot3 + dot4) * 0.25f;

            // ---- L_pos ----
            float dist = 0.0f;
            #pragma unroll
            for (int i = 0; i < 4; i++)
                dist += norm2f(px[i]-gx[i], py[i]-gy[i]);
            dist *= 0.25f;

            const float pax1 = px[1]-px[0], pay1 = py[1]-py[0];
            const float pax2 = px[2]-px[0], pay2 = py[2]-py[0];
            const float pax3 = px[3]-px[0], pay3 = py[3]-py[0];
            const float pred_area = 0.5f * fabsf(pax1*pay2 - pay1*pax2)
                                  + 0.5f * fabsf(pax2*pay3 - pay2*pax3);
            const float gax1 = gx[1]-gx[0], gay1 = gy[1]-gy[0];
            const float gax2 = gx[2]-gx[0], gay2 = gy[2]-gy[0];
            const float gax3 = gx[3]-gx[0], gay3 = gy[3]-gy[0];
            const float gt_area = 0.5f * fabsf(gax1*gay2 - gay1*gax2)
                                + 0.5f * fabsf(gax2*gay3 - gay2*gax3);
            const float area_ratio = __fdividef(fabsf(pred_area - gt_area), gt_area + EPS);

            const float pmx = 0.25f * (px[0]+px[1]+px[2]+px[3]);
            const float pmy = 0.25f * (py[0]+py[1]+py[2]+py[3]);
            const float gmx = 0.25f * (gx[0]+gx[1]+gx[2]+gx[3]);
            const float gmy = 0.25f * (gy[0]+gy[1]+gy[2]+gy[3]);
            float rel_cons = 0.0f;
            #pragma unroll
            for (int i = 0; i < 4; i++)
                rel_cons += norm2f((px[i]-pmx) - (gx[i]-gmx),
                                   (py[i]-pmy) - (gy[i]-gmy));
            rel_cons *= 0.25f;

            const float L_pos = 0.4f * dist + 0.3f * area_ratio + 0.3f * rel_cons;

            L = 0.4f * L_shape + 0.3f * L_edge + 0.3f * L_pos;
            cnt = 1.0f;
        }
    }

    // ---- block reduction (deterministic tree) ----
    #pragma unroll
    for (int off = 16; off > 0; off >>= 1) {
        L   += __shfl_down_sync(0xffffffffu, L,   off);
        cnt += __shfl_down_sync(0xffffffffu, cnt, off);
    }
    const int warp = tid >> 5;
    const int lane = tid & 31;
    if (lane == 0) { sL[warp] = L; sC[warp] = cnt; }
    __syncthreads();

    // ---- one atomic pair per block, last block finalizes ----
    if (tid == 0) {
        float tL = 0.0f, tC = 0.0f;
        #pragma unroll
        for (int w = 0; w < BLOCK / 32; w++) { tL += sL[w]; tC += sC[w]; }
        atomicAdd(&g_sumL, tL);
        atomicAdd(&g_sumC, tC);
        __threadfence();
        const unsigned int old = atomicAdd(&g_count, 1u);
        sIsLast = (old == gridDim.x - 1) ? 1 : 0;
    }
    __syncthreads();

    if (sIsLast && tid == 0) {
        const float tL = g_sumL;
        const float tC = g_sumC;
        out[0] = (tC > 0.5f) ? (tL / tC) : 0.0f;
        g_sumL = 0.0f;      // reset for next graph replay
        g_sumC = 0.0f;
        g_count = 0;
    }
}

extern "C" void kernel_launch(void* const* d_in, const int* in_sizes, int n_in,
                              void* d_out, int out_size)
{
    const float* pred = (const float*)d_in[0];
    const float* gt   = (const float*)d_in[1];
    float* out = (float*)d_out;

    const int nrows = in_sizes[0] / 24;                  // 524288
    const int nblocks = (nrows + BLOCK - 1) / BLOCK;     // 2048

    gsc_fused_kernel<<<nblocks, BLOCK>>>(pred, gt, out, nrows);
}